// round 5
// baseline (speedup 1.0000x reference)
#include <cuda_runtime.h>
#include <cuda_bf16.h>
#include <cstdint>
#include <math.h>

#define BATCH 8
#define HH 256
#define WW 256
#define PLANE (HH*WW)

typedef unsigned long long ull;

// Scratch (device globals: allocation-guard safe)
__device__ float g_bufA[BATCH*32*PLANE];            // conv outputs (32ch)
__device__ float g_bufB[BATCH*128*PLANE];           // irnn outputs (128ch)
__device__ __align__(16) float g_wT[32*32*9*2];     // conv_in f32x2 weights
__device__ __align__(128) uint32_t g_Afr[8*2*9*2*32*4]; // A fragments (bf16x2 words)

// ========================= PTX helpers =========================
__device__ __forceinline__ unsigned smem_u32g(const void* p) {
    return (unsigned)__cvta_generic_to_shared(p);
}
__device__ __forceinline__ void cp_async4(unsigned dst, const void* src, bool pred) {
    asm volatile("cp.async.ca.shared.global [%0], [%1], 4, %2;"
                 :: "r"(dst), "l"(src), "r"(pred ? 4u : 0u));
}
__device__ __forceinline__ void cp_async16(unsigned dst, const void* src, bool pred) {
    asm volatile("cp.async.cg.shared.global [%0], [%1], 16, %2;"
                 :: "r"(dst), "l"(src), "r"(pred ? 16u : 0u));
}
__device__ __forceinline__ void cp_commit() { asm volatile("cp.async.commit_group;"); }
template<int N> __device__ __forceinline__ void cp_wait() {
    asm volatile("cp.async.wait_group %0;" :: "n"(N));
}
// f32x2 packed math (conv_in path)
__device__ __forceinline__ ull pack2(float lo, float hi) {
    ull d; asm("mov.b64 %0, {%1, %2};" : "=l"(d)
        : "r"(__float_as_uint(lo)), "r"(__float_as_uint(hi)));
    return d;
}
__device__ __forceinline__ void unpack2(ull v, float& lo, float& hi) {
    unsigned a, b; asm("mov.b64 {%0, %1}, %2;" : "=r"(a), "=r"(b) : "l"(v));
    lo = __uint_as_float(a); hi = __uint_as_float(b);
}
__device__ __forceinline__ ull fma2(ull a, ull b, ull c) {
    ull d; asm("fma.rn.f32x2 %0, %1, %2, %3;" : "=l"(d) : "l"(a), "l"(b), "l"(c));
    return d;
}
// mma.sync m16n8k16 row.col f32.bf16.bf16.f32 (sm_80+, valid on plain sm_100)
__device__ __forceinline__ void mma_bf16(float* d, const uint32_t* a, uint32_t b0, uint32_t b1) {
    asm volatile("mma.sync.aligned.m16n8k16.row.col.f32.bf16.bf16.f32 "
        "{%0,%1,%2,%3}, {%4,%5,%6,%7}, {%8,%9}, {%0,%1,%2,%3};"
        : "+f"(d[0]), "+f"(d[1]), "+f"(d[2]), "+f"(d[3])
        : "r"(a[0]), "r"(a[1]), "r"(a[2]), "r"(a[3]), "r"(b0), "r"(b1));
}
// pack two floats to bf16x2 (low half = x0)
__device__ __forceinline__ uint32_t bf16x2(float x0, float x1) {
    uint32_t r;
    asm("cvt.rn.bf16x2.f32 %0, %1, %2;" : "=r"(r) : "f"(x1), "f"(x0));
    return r;
}

// ========================= weight prep =========================
// conv_in: w[co][ci][9] -> f32x2-duplicated [ci][co][9]
__global__ void wtrans_kernel(const float* __restrict__ w, float* __restrict__ wd, int cin)
{
    int i = blockIdx.x*blockDim.x + threadIdx.x;
    if (i >= 32*cin*9) return;
    int k  = i % 9;
    int ci = (i/9) % cin;
    int co = i/(9*cin);
    float v = w[i];
    int o = ((ci*32 + co)*9 + k)*2;
    wd[o] = v; wd[o+1] = v;
}

// A-fragment prep for mma.sync: w[cout32][cin128][3][3] fp32 ->
// Afr[ch8][sec2][kt9][mt2][lane32][reg4] bf16x2 words, per PTX m16n8k16 A layout.
// k-in-tile = cin_local (16 per tap), ktile = tap index.
__global__ void wprepA_kernel(const float* __restrict__ w, uint32_t* __restrict__ out)
{
    int i = blockIdx.x*blockDim.x + threadIdx.x;
    if (i >= 8*2*9*2*32*4) return;
    int reg  = i % 4;
    int lane = (i/4) % 32;
    int mt   = (i/128) % 2;
    int kt   = (i/256) % 9;
    int sec  = (i/2304) % 2;
    int ch   = i/4608;
    int g = lane >> 2, tq = lane & 3;
    int cout = mt*16 + g + ((reg & 1) ? 8 : 0);
    int ciL  = 2*tq + ((reg >= 2) ? 8 : 0);
    int ci0  = ch*16 + ciL;
    int kh = kt/3, kw = kt%3;
    float w0 = w[((cout*128 + ci0)*3 + kh)*3 + kw];
    float w1 = w[((cout*128 + ci0 + 1)*3 + kh)*3 + kw];
    float h0 = __bfloat162float(__float2bfloat16_rn(w0));
    float h1 = __bfloat162float(__float2bfloat16_rn(w1));
    uint32_t v;
    if (sec == 0) v = bf16x2(h0, h1);
    else          v = bf16x2(w0 - h0, w1 - h1);
    out[i] = v;
}

// ========================= mma.sync conv (128->32) =========================
// CTA = 128 thr (4 warps), computes 32 couts x 128 pixels (half row h).
// 8 chunks of 16 cin; each chunk: 9 ktiles (taps) x k16 (cin_local).
// bf16x3: D += AhiBhi + AloBhi + AhiBlo.
// smem: B [sec2][n128][96 words, swizzled] @0 (98304 B)
//       A slabs double @98304 (2x18432)
//       raw fp32 double @135168 (2x 16ci x 3r x 136col x 4B)
#define SB_OFF   0
#define SA_OFF   98304
#define SR_OFF   135168
#define CM_SMEM  187392
#define SECW     12288   // words per B section (128*96)

__global__ void __launch_bounds__(128, 1) conv_mma_kernel(
    const float* __restrict__ in, const uint32_t* __restrict__ Afr,
    float* __restrict__ out, const float* __restrict__ mask_w, int epi)
{
    extern __shared__ char smem[];
    uint32_t* Bw   = (uint32_t*)(smem + SB_OFF);
    float*    sraw = (float*)   (smem + SR_OFF);

    const int w0 = blockIdx.x * 128;
    const int h  = blockIdx.y;
    const int b  = blockIdx.z;
    const int tid = threadIdx.x;
    const int wn  = tid >> 5;
    const int lane = tid & 31;
    const int g = lane >> 2, tq = lane & 3;

    float d[2][4][4];
    #pragma unroll
    for (int m = 0; m < 2; ++m)
        #pragma unroll
        for (int j = 0; j < 4; ++j)
            #pragma unroll
            for (int r = 0; r < 4; ++r) d[m][j][r] = 0.f;

    auto prefetch = [&](int c) {
        int buf = c & 1;
        // raw input: rows h-1..h+1, 16 ci, cols [w0-4, w0+132) in float4 groups
        const float* ibase = in + ((size_t)b*128 + c*16)*PLANE;
        unsigned rdst = smem_u32g(sraw + buf*6528);
        for (int i = tid; i < 1632; i += 128) {
            int ci = i / 102, rem = i - ci*102;
            int r  = rem / 34, a = rem - r*34;
            int gh = h - 1 + r, gw = w0 - 4 + 4*a;
            bool ok = ((unsigned)gh < HH) && (gw >= 0) && (gw < WW);
            const float* src = ibase + (size_t)ci*PLANE + (ok ? gh*WW + gw : 0);
            cp_async16(rdst + (ci*408 + r*136 + 4*a)*4, src, ok);
        }
        // A slab: 18432 B
        const char* asrc = (const char*)(Afr + c*4608);
        unsigned adst = smem_u32g(smem + SA_OFF + buf*18432);
        for (int i = tid; i < 1152; i += 128)
            cp_async16(adst + i*16, asrc + i*16, true);
        cp_commit();
    };

    prefetch(0);

    for (int c = 0; c < 8; ++c) {
        if (c < 7) { prefetch(c+1); cp_wait<1>(); }
        else       { cp_wait<0>(); }
        __syncthreads();   // raw[c]/A[c] visible; prior chunk's B reads done

        // ---- build B (im2col, bf16 hi/lo) into swizzled smem ----
        const float* rb = sraw + (c & 1)*6528;
        for (int i = tid; i < 3144; i += 128) {
            int jj = i % 131;            // raw col j = 3 + jj
            int r  = (i/131) % 3;
            int cp = i/393;
            int j  = 3 + jj;
            float x0 = rb[(2*cp)*408 + r*136 + j];
            float x1 = rb[(2*cp+1)*408 + r*136 + j];
            float h0f = __bfloat162float(__float2bfloat16_rn(x0));
            float h1f = __bfloat162float(__float2bfloat16_rn(x1));
            uint32_t hw = bf16x2(h0f, h1f);
            uint32_t lw = bf16x2(x0 - h0f, x1 - h1f);
            #pragma unroll
            for (int kw = 0; kw < 3; ++kw) {
                int n = j - 3 - kw;
                if ((unsigned)n < 128u) {
                    int kword = (r*3 + kw)*8 + cp;
                    int sw = kword ^ ((n & 7) << 2) ^ ((n >> 3) & 3);
                    Bw[n*96 + sw]        = hw;
                    Bw[SECW + n*96 + sw] = lw;
                }
            }
        }
        __syncthreads();   // B visible

        // ---- mma loop ----
        const uint32_t* Asl = (const uint32_t*)(smem + SA_OFF + (c & 1)*18432);
        #pragma unroll
        for (int kt = 0; kt < 9; ++kt) {
            uint4 ah0 = *(const uint4*)&Asl[((0*9 + kt)*2 + 0)*128 + lane*4];
            uint4 ah1 = *(const uint4*)&Asl[((0*9 + kt)*2 + 1)*128 + lane*4];
            uint4 al0 = *(const uint4*)&Asl[((1*9 + kt)*2 + 0)*128 + lane*4];
            uint4 al1 = *(const uint4*)&Asl[((1*9 + kt)*2 + 1)*128 + lane*4];
            #pragma unroll
            for (int j = 0; j < 4; ++j) {
                int n  = wn*32 + j*8 + g;
                int rbse = n*96;
                int k0 = kt*8 + tq;
                int sw0 = (k0)     ^ (g << 2) ^ j;
                int sw1 = (k0 + 4) ^ (g << 2) ^ j;
                uint32_t bh0 = Bw[rbse + sw0];
                uint32_t bh1 = Bw[rbse + sw1];
                uint32_t bl0 = Bw[SECW + rbse + sw0];
                uint32_t bl1 = Bw[SECW + rbse + sw1];
                mma_bf16(d[0][j], (const uint32_t*)&ah0, bh0, bh1);
                mma_bf16(d[1][j], (const uint32_t*)&ah1, bh0, bh1);
                mma_bf16(d[0][j], (const uint32_t*)&al0, bh0, bh1);
                mma_bf16(d[1][j], (const uint32_t*)&al1, bh0, bh1);
                mma_bf16(d[0][j], (const uint32_t*)&ah0, bl0, bl1);
                mma_bf16(d[1][j], (const uint32_t*)&ah1, bl0, bl1);
            }
        }
    }

    // ---- epilogue ----
    if (epi == 0) {
        #pragma unroll
        for (int mt = 0; mt < 2; ++mt) {
            #pragma unroll
            for (int j = 0; j < 4; ++j) {
                int cout = mt*16 + g;
                int col  = w0 + wn*32 + j*8 + 2*tq;
                float2 v01 = make_float2(d[mt][j][0], d[mt][j][1]);
                float2 v23 = make_float2(d[mt][j][2], d[mt][j][3]);
                *(float2*)&out[(((size_t)b*32 + cout)*HH + h)*WW + col]     = v01;
                *(float2*)&out[(((size_t)b*32 + cout + 8)*HH + h)*WW + col] = v23;
            }
        }
    } else {
        float mw0 = __ldg(&mask_w[g]);
        float mw1 = __ldg(&mask_w[g + 8]);
        float mw2 = __ldg(&mask_w[g + 16]);
        float mw3 = __ldg(&mask_w[g + 24]);
        #pragma unroll
        for (int j = 0; j < 4; ++j) {
            float s0 = mw0*fmaxf(d[0][j][0], 0.f) + mw1*fmaxf(d[0][j][2], 0.f)
                     + mw2*fmaxf(d[1][j][0], 0.f) + mw3*fmaxf(d[1][j][2], 0.f);
            float s1 = mw0*fmaxf(d[0][j][1], 0.f) + mw1*fmaxf(d[0][j][3], 0.f)
                     + mw2*fmaxf(d[1][j][1], 0.f) + mw3*fmaxf(d[1][j][3], 0.f);
            #pragma unroll
            for (int off = 4; off < 32; off <<= 1) {
                s0 += __shfl_xor_sync(0xffffffffu, s0, off);
                s1 += __shfl_xor_sync(0xffffffffu, s1, off);
            }
            if (g == 0) {
                int col = w0 + wn*32 + j*8 + 2*tq;
                float2 v = make_float2(1.f/(1.f + expf(-s0)), 1.f/(1.f + expf(-s1)));
                *(float2*)&out[((size_t)b*HH + h)*WW + col] = v;
            }
        }
    }
}

// ========================= conv_in (32->32), FFMA2 path =========================
__global__ void __launch_bounds__(256, 3) conv_in_kernel(
    const float* __restrict__ in, const float* __restrict__ wdup, float* __restrict__ out)
{
    __shared__ float s_in[2][4*350];
    __shared__ __align__(16) float2 s_w[2][4*288];
    const int b = blockIdx.z, oh0 = blockIdx.y*8, ow0 = blockIdx.x*32;
    const int tid = threadIdx.x;
    const int cg = tid >> 6, p = tid & 63, r = p >> 3, cb = (p & 7) << 2;

    ull acc[8][2];
    #pragma unroll
    for (int co = 0; co < 8; ++co) { acc[co][0] = 0ull; acc[co][1] = 0ull; }

    auto load_stage = [&](int c0, int buf) {
        const float* base = in + ((size_t)b*32 + c0)*PLANE;
        for (int i = tid; i < 4*340; i += 256) {
            int ci = i/340, rem = i - ci*340;
            int tr = rem/34, tc = rem - tr*34;
            int gh = oh0 - 1 + tr, gw = ow0 - 1 + tc;
            bool ok = ((unsigned)gh < HH) && ((unsigned)gw < WW);
            const float* src = base + (size_t)ci*PLANE + (ok ? gh*WW + gw : 0);
            cp_async4(smem_u32g(&s_in[buf][ci*350 + tr*35 + tc]), src, ok);
        }
        const float4* wsrc = (const float4*)(wdup + (size_t)c0*576);
        float4* wdst = (float4*)&s_w[buf][0];
        for (int i = tid; i < 576; i += 256)
            cp_async16(smem_u32g(&wdst[i]), &wsrc[i], true);
        cp_commit();
    };

    load_stage(0, 0);
    for (int st = 0; st < 8; ++st) {
        if (st + 1 < 8) { load_stage((st+1)*4, (st+1)&1); cp_wait<1>(); }
        else            { cp_wait<0>(); }
        __syncthreads();
        const float*  si  = &s_in[st&1][0];
        const float2* swb = &s_w[st&1][0];
        #pragma unroll
        for (int ci = 0; ci < 4; ++ci) {
            const float*  sp = si + ci*350 + r*35 + cb;
            const float2* wp = swb + ci*288 + cg*72;
            #pragma unroll
            for (int kh = 0; kh < 3; ++kh) {
                const float* rowp = sp + kh*35;
                float x0=rowp[0],x1=rowp[1],x2=rowp[2],x3=rowp[3],x4=rowp[4],x5=rowp[5];
                ull P0=pack2(x0,x1),P1=pack2(x1,x2),P2=pack2(x2,x3),P3=pack2(x3,x4),P4=pack2(x4,x5);
                #pragma unroll
                for (int co = 0; co < 8; ++co) {
                    const float2* wq = wp + co*9 + kh*3;
                    ull w0=*(const ull*)&wq[0], w1=*(const ull*)&wq[1], w2=*(const ull*)&wq[2];
                    acc[co][0]=fma2(w0,P0,acc[co][0]); acc[co][1]=fma2(w0,P2,acc[co][1]);
                    acc[co][0]=fma2(w1,P1,acc[co][0]); acc[co][1]=fma2(w1,P3,acc[co][1]);
                    acc[co][0]=fma2(w2,P2,acc[co][0]); acc[co][1]=fma2(w2,P4,acc[co][1]);
                }
            }
        }
        __syncthreads();
    }
    const int oh = oh0 + r, ow = ow0 + cb;
    #pragma unroll
    for (int co = 0; co < 8; ++co) {
        float4 v;
        unpack2(acc[co][0], v.x, v.y);
        unpack2(acc[co][1], v.z, v.w);
        *(float4*)&out[(((size_t)b*32 + cg*8 + co)*HH + oh)*WW + ow] = v;
    }
}

// ========================= scans =========================
__global__ void scan_v_kernel(const float* __restrict__ in, float* __restrict__ out,
                              const float* __restrict__ wv, const float* __restrict__ bv)
{
    int tid = blockIdx.x*blockDim.x + threadIdx.x;
    int w = tid & (WW-1);
    int c = (tid >> 8) & 31;
    int b = tid >> 13;
    const float wu = wv[0*32+c], bu = bv[0*32+c];
    const float wd = wv[2*32+c], bd = bv[2*32+c];
    const float* xp = in  + ((size_t)(b*32 + c))*PLANE + w;
    float* outU = out + ((size_t)(b*128 +  0 + c))*PLANE + w;
    float* outD = out + ((size_t)(b*128 + 64 + c))*PLANE + w;
    float s = xp[0];
    outD[0] = s;
    #pragma unroll 4
    for (int h = 1; h < HH; ++h) { s = fmaxf(fmaf(wd, s, xp[h*WW] + bd), 0.f); outD[h*WW] = s; }
    s = xp[(HH-1)*WW];
    outU[(HH-1)*WW] = s;
    #pragma unroll 4
    for (int h = HH-2; h >= 0; --h) { s = fmaxf(fmaf(wu, s, xp[h*WW] + bu), 0.f); outU[h*WW] = s; }
}

__global__ void __launch_bounds__(128) scan_h_kernel(
    const float* __restrict__ in, float* __restrict__ out,
    const float* __restrict__ wv, const float* __restrict__ bv)
{
    __shared__ float sm[128][33];
    const int half = blockIdx.x, c = blockIdx.y, b = blockIdx.z;
    const int tid = threadIdx.x;
    const float wr = wv[1*32+c], br = bv[1*32+c];
    const float wl = wv[3*32+c], bl = bv[3*32+c];
    const float* xp = in  + ((size_t)(b*32 + c))*PLANE + (size_t)half*128*WW;
    float* outR = out + ((size_t)(b*128 + 32 + c))*PLANE + (size_t)half*128*WW;
    float* outL = out + ((size_t)(b*128 + 96 + c))*PLANE + (size_t)half*128*WW;
    float s = 0.f;
    for (int ch = 0; ch < 8; ++ch) {
        const int w0 = ch*32;
        #pragma unroll
        for (int k = 0; k < 8; ++k) {
            int f4 = k*128 + tid, row = f4 >> 3, col4 = (f4 & 7) << 2;
            float4 v = *(const float4*)&xp[row*WW + w0 + col4];
            sm[row][col4]=v.x; sm[row][col4+1]=v.y; sm[row][col4+2]=v.z; sm[row][col4+3]=v.w;
        }
        __syncthreads();
        #pragma unroll
        for (int w = 0; w < 32; ++w) {
            float x = sm[tid][w];
            s = (ch == 0 && w == 0) ? x : fmaxf(fmaf(wr, s, x + br), 0.f);
            sm[tid][w] = s;
        }
        __syncthreads();
        #pragma unroll
        for (int k = 0; k < 8; ++k) {
            int f4 = k*128 + tid, row = f4 >> 3, col4 = (f4 & 7) << 2;
            *(float4*)&outR[row*WW + w0 + col4] =
                make_float4(sm[row][col4], sm[row][col4+1], sm[row][col4+2], sm[row][col4+3]);
        }
        __syncthreads();
    }
    s = 0.f;
    for (int ch = 7; ch >= 0; --ch) {
        const int w0 = ch*32;
        #pragma unroll
        for (int k = 0; k < 8; ++k) {
            int f4 = k*128 + tid, row = f4 >> 3, col4 = (f4 & 7) << 2;
            float4 v = *(const float4*)&xp[row*WW + w0 + col4];
            sm[row][col4]=v.x; sm[row][col4+1]=v.y; sm[row][col4+2]=v.z; sm[row][col4+3]=v.w;
        }
        __syncthreads();
        #pragma unroll
        for (int w = 31; w >= 0; --w) {
            float x = sm[tid][w];
            s = (ch == 7 && w == 31) ? x : fmaxf(fmaf(wl, s, x + bl), 0.f);
            sm[tid][w] = s;
        }
        __syncthreads();
        #pragma unroll
        for (int k = 0; k < 8; ++k) {
            int f4 = k*128 + tid, row = f4 >> 3, col4 = (f4 & 7) << 2;
            *(float4*)&outL[row*WW + w0 + col4] =
                make_float4(sm[row][col4], sm[row][col4+1], sm[row][col4+2], sm[row][col4+3]);
        }
        __syncthreads();
    }
}

// ========================= launcher =========================
extern "C" void kernel_launch(void* const* d_in, const int* in_sizes, int n_in,
                              void* d_out, int out_size)
{
    const float* x          = (const float*)d_in[0];
    const float* conv_in_w  = (const float*)d_in[1];
    const float* conv2_w    = (const float*)d_in[2];
    const float* conv3_w    = (const float*)d_in[3];
    const float* conv_out_w = (const float*)d_in[4];
    const float* irnn1_w    = (const float*)d_in[5];
    const float* irnn1_b    = (const float*)d_in[6];
    const float* irnn2_w    = (const float*)d_in[7];
    const float* irnn2_b    = (const float*)d_in[8];
    float* out = (float*)d_out;

    float* A;  cudaGetSymbolAddress((void**)&A,  g_bufA);
    float* Bb; cudaGetSymbolAddress((void**)&Bb, g_bufB);
    float* Wt; cudaGetSymbolAddress((void**)&Wt, g_wT);
    uint32_t* Af; cudaGetSymbolAddress((void**)&Af, g_Afr);

    cudaFuncSetAttribute(conv_mma_kernel,
                         cudaFuncAttributeMaxDynamicSharedMemorySize, CM_SMEM);

    dim3 cgrid(WW/32, HH/8, BATCH);
    dim3 mgrid(2, HH, BATCH);
    dim3 hgrid(2, 32, BATCH);

    // conv_in (32->32)
    wtrans_kernel<<<(32*32*9 + 255)/256, 256>>>(conv_in_w, Wt, 32);
    conv_in_kernel<<<cgrid, 256>>>(x, Wt, A);
    // irnn1
    scan_v_kernel<<<BATCH*32*WW/256, 256>>>(A, Bb, irnn1_w, irnn1_b);
    scan_h_kernel<<<hgrid, 128>>>(A, Bb, irnn1_w, irnn1_b);
    // conv2 (128->32) via mma.sync
    wprepA_kernel<<<144, 256>>>(conv2_w, Af);
    conv_mma_kernel<<<mgrid, 128, CM_SMEM>>>(Bb, Af, A, nullptr, 0);
    // irnn2
    scan_v_kernel<<<BATCH*32*WW/256, 256>>>(A, Bb, irnn2_w, irnn2_b);
    scan_h_kernel<<<hgrid, 128>>>(A, Bb, irnn2_w, irnn2_b);
    // conv3 (128->32) + relu + 1x1 + sigmoid fused
    wprepA_kernel<<<144, 256>>>(conv3_w, Af);
    conv_mma_kernel<<<mgrid, 128, CM_SMEM>>>(Bb, Af, out, conv_out_w, 1);
}

// round 6
// speedup vs baseline: 2.3591x; 2.3591x over previous
#include <cuda_runtime.h>
#include <cuda_bf16.h>
#include <cstdint>
#include <math.h>

#define BATCH 8
#define HH 256
#define WW 256
#define PLANE (HH*WW)

typedef unsigned long long ull;

// Scratch (device globals: allocation-guard safe)
__device__ float g_bufA[BATCH*32*PLANE];                // conv outputs (32ch fp32)
__device__ ull   g_pk[BATCH*64*PLANE];                  // irnn outputs packed {hi,lo} bf16x2 per cin-pair
__device__ __align__(16) float g_wT[32*32*9*2];         // conv_in f32x2 weights
__device__ __align__(128) uint32_t g_Afr[8*2*9*2*32*4]; // A fragments (bf16x2 words)

// ========================= PTX helpers =========================
__device__ __forceinline__ unsigned smem_u32g(const void* p) {
    return (unsigned)__cvta_generic_to_shared(p);
}
__device__ __forceinline__ void cp_async4(unsigned dst, const void* src, bool pred) {
    asm volatile("cp.async.ca.shared.global [%0], [%1], 4, %2;"
                 :: "r"(dst), "l"(src), "r"(pred ? 4u : 0u));
}
__device__ __forceinline__ void cp_async16(unsigned dst, const void* src, bool pred) {
    asm volatile("cp.async.cg.shared.global [%0], [%1], 16, %2;"
                 :: "r"(dst), "l"(src), "r"(pred ? 16u : 0u));
}
__device__ __forceinline__ void cp_commit() { asm volatile("cp.async.commit_group;"); }
template<int N> __device__ __forceinline__ void cp_wait() {
    asm volatile("cp.async.wait_group %0;" :: "n"(N));
}
// f32x2 packed math (conv_in path)
__device__ __forceinline__ ull pack2(float lo, float hi) {
    ull d; asm("mov.b64 %0, {%1, %2};" : "=l"(d)
        : "r"(__float_as_uint(lo)), "r"(__float_as_uint(hi)));
    return d;
}
__device__ __forceinline__ void unpack2(ull v, float& lo, float& hi) {
    unsigned a, b; asm("mov.b64 {%0, %1}, %2;" : "=r"(a), "=r"(b) : "l"(v));
    lo = __uint_as_float(a); hi = __uint_as_float(b);
}
__device__ __forceinline__ ull fma2(ull a, ull b, ull c) {
    ull d; asm("fma.rn.f32x2 %0, %1, %2, %3;" : "=l"(d) : "l"(a), "l"(b), "l"(c));
    return d;
}
// mma.sync m16n8k16 row.col f32.bf16.bf16.f32
__device__ __forceinline__ void mma_bf16(float* d, const uint32_t* a, uint32_t b0, uint32_t b1) {
    asm volatile("mma.sync.aligned.m16n8k16.row.col.f32.bf16.bf16.f32 "
        "{%0,%1,%2,%3}, {%4,%5,%6,%7}, {%8,%9}, {%0,%1,%2,%3};"
        : "+f"(d[0]), "+f"(d[1]), "+f"(d[2]), "+f"(d[3])
        : "r"(a[0]), "r"(a[1]), "r"(a[2]), "r"(a[3]), "r"(b0), "r"(b1));
}
// pack two floats to bf16x2 (low half = x0)
__device__ __forceinline__ uint32_t bf16x2(float x0, float x1) {
    uint32_t r;
    asm("cvt.rn.bf16x2.f32 %0, %1, %2;" : "=r"(r) : "f"(x1), "f"(x0));
    return r;
}
// pack (s0,s1) -> u64 {hi bf16x2, lo bf16x2}
__device__ __forceinline__ ull pack_hl(float s0, float s1) {
    uint32_t hi = bf16x2(s0, s1);
    float h0 = __uint_as_float(hi << 16);
    float h1 = __uint_as_float(hi & 0xffff0000u);
    uint32_t lo = bf16x2(s0 - h0, s1 - h1);
    return (ull)hi | ((ull)lo << 32);
}

// ========================= weight prep =========================
// conv_in: w[co][ci][9] -> f32x2-duplicated [ci][co][9]
__global__ void wtrans_kernel(const float* __restrict__ w, float* __restrict__ wd, int cin)
{
    int i = blockIdx.x*blockDim.x + threadIdx.x;
    if (i >= 32*cin*9) return;
    int k  = i % 9;
    int ci = (i/9) % cin;
    int co = i/(9*cin);
    float v = w[i];
    int o = ((ci*32 + co)*9 + k)*2;
    wd[o] = v; wd[o+1] = v;
}

// A-fragment prep: w[cout32][cin128][3][3] fp32 ->
// Afr[ch8][sec2][kt9][mt2][lane32][reg4] bf16x2 words (m16n8k16 A layout).
__global__ void wprepA_kernel(const float* __restrict__ w, uint32_t* __restrict__ out)
{
    int i = blockIdx.x*blockDim.x + threadIdx.x;
    if (i >= 8*2*9*2*32*4) return;
    int reg  = i % 4;
    int lane = (i/4) % 32;
    int mt   = (i/128) % 2;
    int kt   = (i/256) % 9;
    int sec  = (i/2304) % 2;
    int ch   = i/4608;
    int g = lane >> 2, tq = lane & 3;
    int cout = mt*16 + g + ((reg & 1) ? 8 : 0);
    int ciL  = 2*tq + ((reg >= 2) ? 8 : 0);
    int ci0  = ch*16 + ciL;
    int kh = kt/3, kw = kt%3;
    float w0 = w[((cout*128 + ci0)*3 + kh)*3 + kw];
    float w1 = w[((cout*128 + ci0 + 1)*3 + kh)*3 + kw];
    float h0 = __bfloat162float(__float2bfloat16_rn(w0));
    float h1 = __bfloat162float(__float2bfloat16_rn(w1));
    uint32_t v;
    if (sec == 0) v = bf16x2(h0, h1);
    else          v = bf16x2(w0 - h0, w1 - h1);
    out[i] = v;
}

// ========================= mma.sync conv (128->32) =========================
// CTA = 256 thr (8 warps = 2 mt x 4 n-slices), 32 couts x 128 pixels (half row h).
// B arrives PRE-SPLIT from the scans as u64 {hi,lo} bf16x2 per cin-pair:
// smem B layout [r3][cp8][col140] u64 -> shift-at-read im2col.
#define B_U64   (24*140)                       // 3360 u64 per buffer
#define SB_OFF  0                              // 2 x 26880 B
#define SA_OFF  (2*B_U64*8)                    // 53760; A: 2 x 18432
#define SRED_OFF (SA_OFF + 2*18432)            // 90624
#define CM_SMEM (SRED_OFF + 1024)              // 91648

__global__ void __launch_bounds__(256, 2) conv_mma_kernel(
    const ull* __restrict__ pk, const uint32_t* __restrict__ Afr,
    float* __restrict__ out, const float* __restrict__ mask_w, int epi)
{
    extern __shared__ char smem[];
    const int w0 = blockIdx.x * 128;
    const int h  = blockIdx.y;
    const int b  = blockIdx.z;
    const int tid = threadIdx.x;
    const int wn  = tid >> 5;
    const int lane = tid & 31;
    const int g = lane >> 2, tq = lane & 3;
    const int mt = wn >> 2;          // 0/1: couts [mt*16, mt*16+16)
    const int ns = wn & 3;           // n-slice of 32 pixels

    float d[4][4];
    #pragma unroll
    for (int j = 0; j < 4; ++j)
        #pragma unroll
        for (int r = 0; r < 4; ++r) d[j][r] = 0.f;

    auto prefetch = [&](int c) {
        int buf = c & 1;
        const ull* pb = pk + ((size_t)b*64 + c*8)*PLANE;
        unsigned bdst = smem_u32g(smem) + buf*(B_U64*8);
        for (int i = tid; i < 8*3*70; i += 256) {
            int cp = i / 210, rem = i - cp*210;
            int r = rem / 70, g2 = rem - r*70;
            int gh = h - 1 + r, gw = w0 - 4 + 2*g2;
            bool ok = ((unsigned)gh < HH) && ((unsigned)gw < WW);
            const ull* src = pb + (size_t)cp*PLANE + (ok ? gh*WW + gw : 0);
            cp_async16(bdst + ((r*8 + cp)*140 + 2*g2)*8, src, ok);
        }
        const char* asrc = (const char*)(Afr + c*4608);
        unsigned adst = smem_u32g(smem) + SA_OFF + buf*18432;
        for (int i = tid; i < 1152; i += 256)
            cp_async16(adst + i*16, asrc + i*16, true);
        cp_commit();
    };

    prefetch(0);

    for (int c = 0; c < 8; ++c) {
        if (c < 7) { prefetch(c+1); cp_wait<1>(); }
        else       { cp_wait<0>(); }
        __syncthreads();

        const ull* Bs = (const ull*)smem + (c & 1)*B_U64;
        const uint32_t* Asl = (const uint32_t*)(smem + SA_OFF + (c & 1)*18432);

        #pragma unroll
        for (int kt = 0; kt < 9; ++kt) {
            const int kh = kt/3, kw = kt - 3*(kt/3);
            uint4 ah = *(const uint4*)&Asl[((0*9 + kt)*2 + mt)*128 + lane*4];
            uint4 al = *(const uint4*)&Asl[((1*9 + kt)*2 + mt)*128 + lane*4];
            #pragma unroll
            for (int j = 0; j < 4; ++j) {
                int col = ns*32 + j*8 + g + kw + 3;
                uint2 b0 = *(const uint2*)&Bs[(kh*8 + tq)*140 + col];
                uint2 b1 = *(const uint2*)&Bs[(kh*8 + tq + 4)*140 + col];
                mma_bf16(d[j], (const uint32_t*)&ah, b0.x, b1.x);   // Ahi*Bhi
                mma_bf16(d[j], (const uint32_t*)&al, b0.x, b1.x);   // Alo*Bhi
                mma_bf16(d[j], (const uint32_t*)&ah, b0.y, b1.y);   // Ahi*Blo
            }
        }
        __syncthreads();
    }

    if (epi == 0) {
        #pragma unroll
        for (int j = 0; j < 4; ++j) {
            int cout = mt*16 + g;
            int col  = w0 + ns*32 + j*8 + 2*tq;
            *(float2*)&out[(((size_t)b*32 + cout)*HH + h)*WW + col]     = make_float2(d[j][0], d[j][1]);
            *(float2*)&out[(((size_t)b*32 + cout + 8)*HH + h)*WW + col] = make_float2(d[j][2], d[j][3]);
        }
    } else {
        float* sred = (float*)(smem + SRED_OFF);
        float mwa = __ldg(&mask_w[mt*16 + g]);
        float mwb = __ldg(&mask_w[mt*16 + g + 8]);
        #pragma unroll
        for (int j = 0; j < 4; ++j) {
            float s0 = mwa*fmaxf(d[j][0], 0.f) + mwb*fmaxf(d[j][2], 0.f);
            float s1 = mwa*fmaxf(d[j][1], 0.f) + mwb*fmaxf(d[j][3], 0.f);
            #pragma unroll
            for (int off = 4; off < 32; off <<= 1) {
                s0 += __shfl_xor_sync(0xffffffffu, s0, off);
                s1 += __shfl_xor_sync(0xffffffffu, s1, off);
            }
            if (g == 0) {
                int coln = ns*32 + j*8 + 2*tq;
                sred[mt*128 + coln]     = s0;
                sred[mt*128 + coln + 1] = s1;
            }
        }
        __syncthreads();
        if (tid < 128) {
            float v = sred[tid] + sred[128 + tid];
            out[((size_t)b*HH + h)*WW + w0 + tid] = 1.f/(1.f + expf(-v));
        }
    }
}

// ========================= conv_in (32->32), FFMA2 path =========================
__global__ void __launch_bounds__(256, 3) conv_in_kernel(
    const float* __restrict__ in, const float* __restrict__ wdup, float* __restrict__ out)
{
    __shared__ float s_in[2][4*350];
    __shared__ __align__(16) float2 s_w[2][4*288];
    const int b = blockIdx.z, oh0 = blockIdx.y*8, ow0 = blockIdx.x*32;
    const int tid = threadIdx.x;
    const int cg = tid >> 6, p = tid & 63, r = p >> 3, cb = (p & 7) << 2;

    ull acc[8][2];
    #pragma unroll
    for (int co = 0; co < 8; ++co) { acc[co][0] = 0ull; acc[co][1] = 0ull; }

    auto load_stage = [&](int c0, int buf) {
        const float* base = in + ((size_t)b*32 + c0)*PLANE;
        for (int i = tid; i < 4*340; i += 256) {
            int ci = i/340, rem = i - ci*340;
            int tr = rem/34, tc = rem - tr*34;
            int gh = oh0 - 1 + tr, gw = ow0 - 1 + tc;
            bool ok = ((unsigned)gh < HH) && ((unsigned)gw < WW);
            const float* src = base + (size_t)ci*PLANE + (ok ? gh*WW + gw : 0);
            cp_async4(smem_u32g(&s_in[buf][ci*350 + tr*35 + tc]), src, ok);
        }
        const float4* wsrc = (const float4*)(wdup + (size_t)c0*576);
        float4* wdst = (float4*)&s_w[buf][0];
        for (int i = tid; i < 576; i += 256)
            cp_async16(smem_u32g(&wdst[i]), &wsrc[i], true);
        cp_commit();
    };

    load_stage(0, 0);
    for (int st = 0; st < 8; ++st) {
        if (st + 1 < 8) { load_stage((st+1)*4, (st+1)&1); cp_wait<1>(); }
        else            { cp_wait<0>(); }
        __syncthreads();
        const float*  si  = &s_in[st&1][0];
        const float2* swb = &s_w[st&1][0];
        #pragma unroll
        for (int ci = 0; ci < 4; ++ci) {
            const float*  sp = si + ci*350 + r*35 + cb;
            const float2* wp = swb + ci*288 + cg*72;
            #pragma unroll
            for (int kh = 0; kh < 3; ++kh) {
                const float* rowp = sp + kh*35;
                float x0=rowp[0],x1=rowp[1],x2=rowp[2],x3=rowp[3],x4=rowp[4],x5=rowp[5];
                ull P0=pack2(x0,x1),P1=pack2(x1,x2),P2=pack2(x2,x3),P3=pack2(x3,x4),P4=pack2(x4,x5);
                #pragma unroll
                for (int co = 0; co < 8; ++co) {
                    const float2* wq = wp + co*9 + kh*3;
                    ull w0=*(const ull*)&wq[0], w1=*(const ull*)&wq[1], w2=*(const ull*)&wq[2];
                    acc[co][0]=fma2(w0,P0,acc[co][0]); acc[co][1]=fma2(w0,P2,acc[co][1]);
                    acc[co][0]=fma2(w1,P1,acc[co][0]); acc[co][1]=fma2(w1,P3,acc[co][1]);
                    acc[co][0]=fma2(w2,P2,acc[co][0]); acc[co][1]=fma2(w2,P4,acc[co][1]);
                }
            }
        }
        __syncthreads();
    }
    const int oh = oh0 + r, ow = ow0 + cb;
    #pragma unroll
    for (int co = 0; co < 8; ++co) {
        float4 v;
        unpack2(acc[co][0], v.x, v.y);
        unpack2(acc[co][1], v.z, v.w);
        *(float4*)&out[(((size_t)b*32 + cg*8 + co)*HH + oh)*WW + ow] = v;
    }
}

// ========================= scans (emit packed {hi,lo} u64) =========================
// channel-pair layout in g_pk: up cpairs 0-15, right 16-31, down 32-47, left 48-63
__global__ void scan_v_kernel(const float* __restrict__ in, ull* __restrict__ pk,
                              const float* __restrict__ wv, const float* __restrict__ bv)
{
    int t = blockIdx.x*blockDim.x + threadIdx.x;   // B*16*W
    int w = t & (WW-1);
    int cp = (t >> 8) & 15;
    int b = t >> 12;
    int c0 = 2*cp, c1 = c0 + 1;
    const float wu0 = wv[c0],    wu1 = wv[c1],    bu0 = bv[c0],    bu1 = bv[c1];
    const float wd0 = wv[64+c0], wd1 = wv[64+c1], bd0 = bv[64+c0], bd1 = bv[64+c1];
    const float* x0 = in + ((size_t)(b*32 + c0))*PLANE + w;
    const float* x1 = in + ((size_t)(b*32 + c1))*PLANE + w;
    ull* oU = pk + ((size_t)(b*64 + cp))*PLANE + w;
    ull* oD = pk + ((size_t)(b*64 + 32 + cp))*PLANE + w;

    float s0 = x0[0], s1 = x1[0];
    oD[0] = pack_hl(s0, s1);
    #pragma unroll 4
    for (int h = 1; h < HH; ++h) {
        s0 = fmaxf(fmaf(wd0, s0, x0[h*WW] + bd0), 0.f);
        s1 = fmaxf(fmaf(wd1, s1, x1[h*WW] + bd1), 0.f);
        oD[h*WW] = pack_hl(s0, s1);
    }
    s0 = x0[(HH-1)*WW]; s1 = x1[(HH-1)*WW];
    oU[(HH-1)*WW] = pack_hl(s0, s1);
    #pragma unroll 4
    for (int h = HH-2; h >= 0; --h) {
        s0 = fmaxf(fmaf(wu0, s0, x0[h*WW] + bu0), 0.f);
        s1 = fmaxf(fmaf(wu1, s1, x1[h*WW] + bu1), 0.f);
        oU[h*WW] = pack_hl(s0, s1);
    }
}

__global__ void __launch_bounds__(128) scan_h_kernel(
    const float* __restrict__ in, ull* __restrict__ pk,
    const float* __restrict__ wv, const float* __restrict__ bv)
{
    __shared__ float sm0[128][33], sm1[128][33];
    const int half = blockIdx.x, cp = blockIdx.y, b = blockIdx.z;
    const int tid = threadIdx.x;
    const int c0 = 2*cp, c1 = c0 + 1;
    const float wr0 = wv[32+c0], wr1 = wv[32+c1], br0 = bv[32+c0], br1 = bv[32+c1];
    const float wl0 = wv[96+c0], wl1 = wv[96+c1], bl0 = bv[96+c0], bl1 = bv[96+c1];
    const float* x0 = in + ((size_t)(b*32 + c0))*PLANE + (size_t)half*128*WW;
    const float* x1 = in + ((size_t)(b*32 + c1))*PLANE + (size_t)half*128*WW;
    ull* oR = pk + ((size_t)(b*64 + 16 + cp))*PLANE + (size_t)half*128*WW;
    ull* oL = pk + ((size_t)(b*64 + 48 + cp))*PLANE + (size_t)half*128*WW;

    float s0 = 0.f, s1 = 0.f;
    for (int ch = 0; ch < 8; ++ch) {
        const int w0 = ch*32;
        #pragma unroll
        for (int k = 0; k < 8; ++k) {
            int f4 = k*128 + tid, row = f4 >> 3, col4 = (f4 & 7) << 2;
            float4 v0 = *(const float4*)&x0[row*WW + w0 + col4];
            float4 v1 = *(const float4*)&x1[row*WW + w0 + col4];
            sm0[row][col4]=v0.x; sm0[row][col4+1]=v0.y; sm0[row][col4+2]=v0.z; sm0[row][col4+3]=v0.w;
            sm1[row][col4]=v1.x; sm1[row][col4+1]=v1.y; sm1[row][col4+2]=v1.z; sm1[row][col4+3]=v1.w;
        }
        __syncthreads();
        #pragma unroll
        for (int w = 0; w < 32; ++w) {
            float a0 = sm0[tid][w], a1 = sm1[tid][w];
            bool fs = (ch == 0 && w == 0);
            s0 = fs ? a0 : fmaxf(fmaf(wr0, s0, a0 + br0), 0.f);
            s1 = fs ? a1 : fmaxf(fmaf(wr1, s1, a1 + br1), 0.f);
            sm0[tid][w] = s0; sm1[tid][w] = s1;
        }
        __syncthreads();
        #pragma unroll
        for (int e = 0; e < 32; ++e) {
            int idx = e*128 + tid, row = idx >> 5, col = idx & 31;
            oR[row*WW + w0 + col] = pack_hl(sm0[row][col], sm1[row][col]);
        }
        __syncthreads();
    }
    s0 = 0.f; s1 = 0.f;
    for (int ch = 7; ch >= 0; --ch) {
        const int w0 = ch*32;
        #pragma unroll
        for (int k = 0; k < 8; ++k) {
            int f4 = k*128 + tid, row = f4 >> 3, col4 = (f4 & 7) << 2;
            float4 v0 = *(const float4*)&x0[row*WW + w0 + col4];
            float4 v1 = *(const float4*)&x1[row*WW + w0 + col4];
            sm0[row][col4]=v0.x; sm0[row][col4+1]=v0.y; sm0[row][col4+2]=v0.z; sm0[row][col4+3]=v0.w;
            sm1[row][col4]=v1.x; sm1[row][col4+1]=v1.y; sm1[row][col4+2]=v1.z; sm1[row][col4+3]=v1.w;
        }
        __syncthreads();
        #pragma unroll
        for (int w = 31; w >= 0; --w) {
            float a0 = sm0[tid][w], a1 = sm1[tid][w];
            bool fs = (ch == 7 && w == 31);
            s0 = fs ? a0 : fmaxf(fmaf(wl0, s0, a0 + bl0), 0.f);
            s1 = fs ? a1 : fmaxf(fmaf(wl1, s1, a1 + bl1), 0.f);
            sm0[tid][w] = s0; sm1[tid][w] = s1;
        }
        __syncthreads();
        #pragma unroll
        for (int e = 0; e < 32; ++e) {
            int idx = e*128 + tid, row = idx >> 5, col = idx & 31;
            oL[row*WW + w0 + col] = pack_hl(sm0[row][col], sm1[row][col]);
        }
        __syncthreads();
    }
}

// ========================= launcher =========================
extern "C" void kernel_launch(void* const* d_in, const int* in_sizes, int n_in,
                              void* d_out, int out_size)
{
    const float* x          = (const float*)d_in[0];
    const float* conv_in_w  = (const float*)d_in[1];
    const float* conv2_w    = (const float*)d_in[2];
    const float* conv3_w    = (const float*)d_in[3];
    const float* conv_out_w = (const float*)d_in[4];
    const float* irnn1_w    = (const float*)d_in[5];
    const float* irnn1_b    = (const float*)d_in[6];
    const float* irnn2_w    = (const float*)d_in[7];
    const float* irnn2_b    = (const float*)d_in[8];
    float* out = (float*)d_out;

    float* A;  cudaGetSymbolAddress((void**)&A,  g_bufA);
    ull*   PK; cudaGetSymbolAddress((void**)&PK, g_pk);
    float* Wt; cudaGetSymbolAddress((void**)&Wt, g_wT);
    uint32_t* Af; cudaGetSymbolAddress((void**)&Af, g_Afr);

    cudaFuncSetAttribute(conv_mma_kernel,
                         cudaFuncAttributeMaxDynamicSharedMemorySize, CM_SMEM);

    dim3 cgrid(WW/32, HH/8, BATCH);
    dim3 mgrid(2, HH, BATCH);
    dim3 hgrid(2, 16, BATCH);

    // conv_in (32->32)
    wtrans_kernel<<<(32*32*9 + 255)/256, 256>>>(conv_in_w, Wt, 32);
    conv_in_kernel<<<cgrid, 256>>>(x, Wt, A);
    // irnn1 -> packed
    scan_v_kernel<<<BATCH*16*WW/256, 256>>>(A, PK, irnn1_w, irnn1_b);
    scan_h_kernel<<<hgrid, 128>>>(A, PK, irnn1_w, irnn1_b);
    // conv2 (128->32) via mma.sync
    wprepA_kernel<<<144, 256>>>(conv2_w, Af);
    conv_mma_kernel<<<mgrid, 256, CM_SMEM>>>(PK, Af, A, nullptr, 0);
    // irnn2 -> packed
    scan_v_kernel<<<BATCH*16*WW/256, 256>>>(A, PK, irnn2_w, irnn2_b);
    scan_h_kernel<<<hgrid, 128>>>(A, PK, irnn2_w, irnn2_b);
    // conv3 (128->32) + relu + 1x1 + sigmoid fused
    wprepA_kernel<<<144, 256>>>(conv3_w, Af);
    conv_mma_kernel<<<mgrid, 256, CM_SMEM>>>(PK, Af, out, conv_out_w, 1);
}

// round 9
// speedup vs baseline: 2.8644x; 1.2142x over previous
#include <cuda_runtime.h>
#include <cuda_bf16.h>
#include <cstdint>
#include <math.h>

#define BATCH 8
#define HH 256
#define WW 256
#define PLANE (HH*WW)

typedef unsigned long long ull;

// Scratch (device globals: allocation-guard safe).
// Resubmission of the round-7 candidate after two broker-side container
// failures; source audited, no kernel-attributable fault found.
__device__ float g_bufA[BATCH*32*PLANE];                // conv outputs (32ch fp32)
__device__ ull   g_pk[BATCH*64*PLANE];                  // packed {hi,lo} bf16x2 per cin-pair
__device__ __align__(128) uint32_t g_Afr[8*2*9*2*32*4]; // A fragments (bf16x2 words)

// ========================= PTX helpers =========================
__device__ __forceinline__ unsigned smem_u32g(const void* p) {
    return (unsigned)__cvta_generic_to_shared(p);
}
__device__ __forceinline__ void cp_async16(unsigned dst, const void* src, bool pred) {
    asm volatile("cp.async.cg.shared.global [%0], [%1], 16, %2;"
                 :: "r"(dst), "l"(src), "r"(pred ? 16u : 0u));
}
__device__ __forceinline__ void cp_commit() { asm volatile("cp.async.commit_group;"); }
template<int N> __device__ __forceinline__ void cp_wait() {
    asm volatile("cp.async.wait_group %0;" :: "n"(N));
}
// mma.sync m16n8k16 row.col f32.bf16.bf16.f32
__device__ __forceinline__ void mma_bf16(float* d, const uint32_t* a, uint32_t b0, uint32_t b1) {
    asm volatile("mma.sync.aligned.m16n8k16.row.col.f32.bf16.bf16.f32 "
        "{%0,%1,%2,%3}, {%4,%5,%6,%7}, {%8,%9}, {%0,%1,%2,%3};"
        : "+f"(d[0]), "+f"(d[1]), "+f"(d[2]), "+f"(d[3])
        : "r"(a[0]), "r"(a[1]), "r"(a[2]), "r"(a[3]), "r"(b0), "r"(b1));
}
// pack two floats to bf16x2 (low half = x0)
__device__ __forceinline__ uint32_t bf16x2(float x0, float x1) {
    uint32_t r;
    asm("cvt.rn.bf16x2.f32 %0, %1, %2;" : "=r"(r) : "f"(x1), "f"(x0));
    return r;
}
// pack (s0,s1) -> u64 {hi bf16x2, lo bf16x2}
__device__ __forceinline__ ull pack_hl(float s0, float s1) {
    uint32_t hi = bf16x2(s0, s1);
    float h0 = __uint_as_float(hi << 16);
    float h1 = __uint_as_float(hi & 0xffff0000u);
    uint32_t lo = bf16x2(s0 - h0, s1 - h1);
    return (ull)hi | ((ull)lo << 32);
}

// ========================= prep kernels =========================
// pack x fp32 (32ch) -> {hi,lo} u64 (16 cpairs)
__global__ void xpack_kernel(const float* __restrict__ x, ull* __restrict__ pk)
{
    int idx = blockIdx.x*blockDim.x + threadIdx.x;   // B*16*PLANE threads
    int p  = idx & (PLANE-1);
    int cp = (idx >> 16) & 15;
    int b  = idx >> 20;
    float v0 = x[((size_t)(b*32 + 2*cp))*PLANE + p];
    float v1 = x[((size_t)(b*32 + 2*cp + 1))*PLANE + p];
    pk[((size_t)(b*16 + cp))*PLANE + p] = pack_hl(v0, v1);
}

// A-fragment prep: w[cout32][CIN][3][3] fp32 ->
// Afr[ch][sec2][kt9][mt2][lane32][reg4] bf16x2 words (m16n8k16 A layout).
template<int CHUNKS>
__global__ void wprepA_kernel(const float* __restrict__ w, uint32_t* __restrict__ out)
{
    constexpr int CIN = CHUNKS*16;
    int i = blockIdx.x*blockDim.x + threadIdx.x;
    if (i >= CHUNKS*4608) return;
    int reg  = i % 4;
    int lane = (i/4) % 32;
    int mt   = (i/128) % 2;
    int kt   = (i/256) % 9;
    int sec  = (i/2304) % 2;
    int ch   = i/4608;
    int g = lane >> 2, tq = lane & 3;
    int cout = mt*16 + g + ((reg & 1) ? 8 : 0);
    int ciL  = 2*tq + ((reg >= 2) ? 8 : 0);
    int ci0  = ch*16 + ciL;
    int kh = kt/3, kw = kt%3;
    float w0 = w[((cout*CIN + ci0)*3 + kh)*3 + kw];
    float w1 = w[((cout*CIN + ci0 + 1)*3 + kh)*3 + kw];
    float h0 = __bfloat162float(__float2bfloat16_rn(w0));
    float h1 = __bfloat162float(__float2bfloat16_rn(w1));
    uint32_t v;
    if (sec == 0) v = bf16x2(h0, h1);
    else          v = bf16x2(w0 - h0, w1 - h1);
    out[i] = v;
}

// ========================= mma.sync conv (CIN->32) =========================
// CTA = 256 thr (8 warps = 2 mt x 4 n-slices), 32 couts x 128 pixels (half row h).
// B pre-split u64 {hi,lo}; smem [r3][cp8][col140] u64; shift-at-read im2col.
#define B_U64   (24*140)
#define SA_OFF  (2*B_U64*8)                    // 53760; A: 2 x 18432
#define SRED_OFF (SA_OFF + 2*18432)            // 90624
#define CM_SMEM (SRED_OFF + 1024)              // 91648

template<int CHUNKS>
__global__ void __launch_bounds__(256, 2) conv_mma_kernel(
    const ull* __restrict__ pk, const uint32_t* __restrict__ Afr,
    float* __restrict__ out, const float* __restrict__ mask_w, int epi)
{
    extern __shared__ char smem[];
    const int w0 = blockIdx.x * 128;
    const int h  = blockIdx.y;
    const int b  = blockIdx.z;
    const int tid = threadIdx.x;
    const int wn  = tid >> 5;
    const int lane = tid & 31;
    const int g = lane >> 2, tq = lane & 3;
    const int mt = wn >> 2;
    const int ns = wn & 3;

    float d[4][4];
    #pragma unroll
    for (int j = 0; j < 4; ++j)
        #pragma unroll
        for (int r = 0; r < 4; ++r) d[j][r] = 0.f;

    auto prefetch = [&](int c) {
        int buf = c & 1;
        const ull* pb = pk + ((size_t)b*(CHUNKS*8) + c*8)*PLANE;
        unsigned bdst = smem_u32g(smem) + buf*(B_U64*8);
        for (int i = tid; i < 8*3*70; i += 256) {
            int cp = i / 210, rem = i - cp*210;
            int r = rem / 70, g2 = rem - r*70;
            int gh = h - 1 + r, gw = w0 - 4 + 2*g2;
            bool ok = ((unsigned)gh < HH) && ((unsigned)gw < WW);
            const ull* src = pb + (size_t)cp*PLANE + (ok ? gh*WW + gw : 0);
            cp_async16(bdst + ((r*8 + cp)*140 + 2*g2)*8, src, ok);
        }
        const char* asrc = (const char*)(Afr + c*4608);
        unsigned adst = smem_u32g(smem) + SA_OFF + buf*18432;
        for (int i = tid; i < 1152; i += 256)
            cp_async16(adst + i*16, asrc + i*16, true);
        cp_commit();
    };

    prefetch(0);

    for (int c = 0; c < CHUNKS; ++c) {
        if (c < CHUNKS-1) { prefetch(c+1); cp_wait<1>(); }
        else              { cp_wait<0>(); }
        __syncthreads();

        const ull* Bs = (const ull*)smem + (c & 1)*B_U64;
        const uint32_t* Asl = (const uint32_t*)(smem + SA_OFF + (c & 1)*18432);

        #pragma unroll
        for (int kt = 0; kt < 9; ++kt) {
            const int kh = kt/3, kw = kt - 3*(kt/3);
            uint4 ah = *(const uint4*)&Asl[((0*9 + kt)*2 + mt)*128 + lane*4];
            uint4 al = *(const uint4*)&Asl[((1*9 + kt)*2 + mt)*128 + lane*4];
            #pragma unroll
            for (int j = 0; j < 4; ++j) {
                int col = ns*32 + j*8 + g + kw + 3;
                uint2 b0 = *(const uint2*)&Bs[(kh*8 + tq)*140 + col];
                uint2 b1 = *(const uint2*)&Bs[(kh*8 + tq + 4)*140 + col];
                mma_bf16(d[j], (const uint32_t*)&ah, b0.x, b1.x);   // Ahi*Bhi
                mma_bf16(d[j], (const uint32_t*)&al, b0.x, b1.x);   // Alo*Bhi
                mma_bf16(d[j], (const uint32_t*)&ah, b0.y, b1.y);   // Ahi*Blo
            }
        }
        __syncthreads();
    }

    if (epi == 0) {
        #pragma unroll
        for (int j = 0; j < 4; ++j) {
            int cout = mt*16 + g;
            int col  = w0 + ns*32 + j*8 + 2*tq;
            *(float2*)&out[(((size_t)b*32 + cout)*HH + h)*WW + col]     = make_float2(d[j][0], d[j][1]);
            *(float2*)&out[(((size_t)b*32 + cout + 8)*HH + h)*WW + col] = make_float2(d[j][2], d[j][3]);
        }
    } else {
        float* sred = (float*)(smem + SRED_OFF);
        float mwa = __ldg(&mask_w[mt*16 + g]);
        float mwb = __ldg(&mask_w[mt*16 + g + 8]);
        #pragma unroll
        for (int j = 0; j < 4; ++j) {
            float s0 = mwa*fmaxf(d[j][0], 0.f) + mwb*fmaxf(d[j][2], 0.f);
            float s1 = mwa*fmaxf(d[j][1], 0.f) + mwb*fmaxf(d[j][3], 0.f);
            #pragma unroll
            for (int off = 4; off < 32; off <<= 1) {
                s0 += __shfl_xor_sync(0xffffffffu, s0, off);
                s1 += __shfl_xor_sync(0xffffffffu, s1, off);
            }
            if (g == 0) {
                int coln = ns*32 + j*8 + 2*tq;
                sred[mt*128 + coln]     = s0;
                sred[mt*128 + coln + 1] = s1;
            }
        }
        __syncthreads();
        if (tid < 128) {
            float v = sred[tid] + sred[128 + tid];
            out[((size_t)b*HH + h)*WW + w0 + tid] = 1.f/(1.f + expf(-v));
        }
    }
}

// ========================= scans (emit packed {hi,lo} u64) =========================
// cpair layout in g_pk: up 0-15, right 16-31, down 32-47, left 48-63.
// Direction split into the grid for 2x warp parallelism on latency-bound scans.
__global__ void scan_v_kernel(const float* __restrict__ in, ull* __restrict__ pk,
                              const float* __restrict__ wv, const float* __restrict__ bv)
{
    int t = blockIdx.x*blockDim.x + threadIdx.x;   // B*2*16*W threads
    int w    = t & (WW-1);
    int cp   = (t >> 8) & 15;
    int down = (t >> 12) & 1;
    int b    = t >> 13;
    int c0 = 2*cp, c1 = c0 + 1;
    const float* x0 = in + ((size_t)(b*32 + c0))*PLANE + w;
    const float* x1 = in + ((size_t)(b*32 + c1))*PLANE + w;

    if (down) {
        const float wd0 = wv[64+c0], wd1 = wv[64+c1], bd0 = bv[64+c0], bd1 = bv[64+c1];
        ull* o = pk + ((size_t)(b*64 + 32 + cp))*PLANE + w;
        float s0 = x0[0], s1 = x1[0];
        o[0] = pack_hl(s0, s1);
        #pragma unroll 4
        for (int h = 1; h < HH; ++h) {
            s0 = fmaxf(fmaf(wd0, s0, x0[h*WW] + bd0), 0.f);
            s1 = fmaxf(fmaf(wd1, s1, x1[h*WW] + bd1), 0.f);
            o[h*WW] = pack_hl(s0, s1);
        }
    } else {
        const float wu0 = wv[c0], wu1 = wv[c1], bu0 = bv[c0], bu1 = bv[c1];
        ull* o = pk + ((size_t)(b*64 + cp))*PLANE + w;
        float s0 = x0[(HH-1)*WW], s1 = x1[(HH-1)*WW];
        o[(HH-1)*WW] = pack_hl(s0, s1);
        #pragma unroll 4
        for (int h = HH-2; h >= 0; --h) {
            s0 = fmaxf(fmaf(wu0, s0, x0[h*WW] + bu0), 0.f);
            s1 = fmaxf(fmaf(wu1, s1, x1[h*WW] + bu1), 0.f);
            o[h*WW] = pack_hl(s0, s1);
        }
    }
}

__global__ void __launch_bounds__(128) scan_h_kernel(
    const float* __restrict__ in, ull* __restrict__ pk,
    const float* __restrict__ wv, const float* __restrict__ bv)
{
    __shared__ float sm0[128][33], sm1[128][33];
    const int q    = blockIdx.x;      // half = q&1, left = q>>1
    const int half = q & 1, left = q >> 1;
    const int cp   = blockIdx.y, b = blockIdx.z;
    const int tid  = threadIdx.x;
    const int c0 = 2*cp, c1 = c0 + 1;
    const float* x0 = in + ((size_t)(b*32 + c0))*PLANE + (size_t)half*128*WW;
    const float* x1 = in + ((size_t)(b*32 + c1))*PLANE + (size_t)half*128*WW;

    if (!left) {
        const float wr0 = wv[32+c0], wr1 = wv[32+c1], br0 = bv[32+c0], br1 = bv[32+c1];
        ull* o = pk + ((size_t)(b*64 + 16 + cp))*PLANE + (size_t)half*128*WW;
        float s0 = 0.f, s1 = 0.f;
        for (int ch = 0; ch < 8; ++ch) {
            const int w0 = ch*32;
            #pragma unroll
            for (int k = 0; k < 8; ++k) {
                int f4 = k*128 + tid, row = f4 >> 3, col4 = (f4 & 7) << 2;
                float4 v0 = *(const float4*)&x0[row*WW + w0 + col4];
                float4 v1 = *(const float4*)&x1[row*WW + w0 + col4];
                sm0[row][col4]=v0.x; sm0[row][col4+1]=v0.y; sm0[row][col4+2]=v0.z; sm0[row][col4+3]=v0.w;
                sm1[row][col4]=v1.x; sm1[row][col4+1]=v1.y; sm1[row][col4+2]=v1.z; sm1[row][col4+3]=v1.w;
            }
            __syncthreads();
            #pragma unroll
            for (int w = 0; w < 32; ++w) {
                float a0 = sm0[tid][w], a1 = sm1[tid][w];
                bool fs = (ch == 0 && w == 0);
                s0 = fs ? a0 : fmaxf(fmaf(wr0, s0, a0 + br0), 0.f);
                s1 = fs ? a1 : fmaxf(fmaf(wr1, s1, a1 + br1), 0.f);
                sm0[tid][w] = s0; sm1[tid][w] = s1;
            }
            __syncthreads();
            #pragma unroll
            for (int e = 0; e < 32; ++e) {
                int idx = e*128 + tid, row = idx >> 5, col = idx & 31;
                o[row*WW + w0 + col] = pack_hl(sm0[row][col], sm1[row][col]);
            }
            __syncthreads();
        }
    } else {
        const float wl0 = wv[96+c0], wl1 = wv[96+c1], bl0 = bv[96+c0], bl1 = bv[96+c1];
        ull* o = pk + ((size_t)(b*64 + 48 + cp))*PLANE + (size_t)half*128*WW;
        float s0 = 0.f, s1 = 0.f;
        for (int ch = 7; ch >= 0; --ch) {
            const int w0 = ch*32;
            #pragma unroll
            for (int k = 0; k < 8; ++k) {
                int f4 = k*128 + tid, row = f4 >> 3, col4 = (f4 & 7) << 2;
                float4 v0 = *(const float4*)&x0[row*WW + w0 + col4];
                float4 v1 = *(const float4*)&x1[row*WW + w0 + col4];
                sm0[row][col4]=v0.x; sm0[row][col4+1]=v0.y; sm0[row][col4+2]=v0.z; sm0[row][col4+3]=v0.w;
                sm1[row][col4]=v1.x; sm1[row][col4+1]=v1.y; sm1[row][col4+2]=v1.z; sm1[row][col4+3]=v1.w;
            }
            __syncthreads();
            #pragma unroll
            for (int w = 31; w >= 0; --w) {
                float a0 = sm0[tid][w], a1 = sm1[tid][w];
                bool fs = (ch == 7 && w == 31);
                s0 = fs ? a0 : fmaxf(fmaf(wl0, s0, a0 + bl0), 0.f);
                s1 = fs ? a1 : fmaxf(fmaf(wl1, s1, a1 + bl1), 0.f);
                sm0[tid][w] = s0; sm1[tid][w] = s1;
            }
            __syncthreads();
            #pragma unroll
            for (int e = 0; e < 32; ++e) {
                int idx = e*128 + tid, row = idx >> 5, col = idx & 31;
                o[row*WW + w0 + col] = pack_hl(sm0[row][col], sm1[row][col]);
            }
            __syncthreads();
        }
    }
}

// ========================= launcher =========================
extern "C" void kernel_launch(void* const* d_in, const int* in_sizes, int n_in,
                              void* d_out, int out_size)
{
    const float* x          = (const float*)d_in[0];
    const float* conv_in_w  = (const float*)d_in[1];
    const float* conv2_w    = (const float*)d_in[2];
    const float* conv3_w    = (const float*)d_in[3];
    const float* conv_out_w = (const float*)d_in[4];
    const float* irnn1_w    = (const float*)d_in[5];
    const float* irnn1_b    = (const float*)d_in[6];
    const float* irnn2_w    = (const float*)d_in[7];
    const float* irnn2_b    = (const float*)d_in[8];
    float* out = (float*)d_out;

    float* A;  cudaGetSymbolAddress((void**)&A,  g_bufA);
    ull*   PK; cudaGetSymbolAddress((void**)&PK, g_pk);
    uint32_t* Af; cudaGetSymbolAddress((void**)&Af, g_Afr);

    cudaFuncSetAttribute(conv_mma_kernel<2>,
                         cudaFuncAttributeMaxDynamicSharedMemorySize, CM_SMEM);
    cudaFuncSetAttribute(conv_mma_kernel<8>,
                         cudaFuncAttributeMaxDynamicSharedMemorySize, CM_SMEM);

    dim3 mgrid(2, HH, BATCH);
    dim3 hgrid(4, 16, BATCH);

    // conv_in (32->32) via mma
    xpack_kernel<<<BATCH*16*PLANE/256, 256>>>(x, PK);
    wprepA_kernel<2><<<36, 256>>>(conv_in_w, Af);
    conv_mma_kernel<2><<<mgrid, 256, CM_SMEM>>>(PK, Af, A, nullptr, 0);
    // irnn1 -> packed
    scan_v_kernel<<<BATCH*2*16*WW/256, 256>>>(A, PK, irnn1_w, irnn1_b);
    scan_h_kernel<<<hgrid, 128>>>(A, PK, irnn1_w, irnn1_b);
    // conv2 (128->32)
    wprepA_kernel<8><<<144, 256>>>(conv2_w, Af);
    conv_mma_kernel<8><<<mgrid, 256, CM_SMEM>>>(PK, Af, A, nullptr, 0);
    // irnn2 -> packed
    scan_v_kernel<<<BATCH*2*16*WW/256, 256>>>(A, PK, irnn2_w, irnn2_b);
    scan_h_kernel<<<hgrid, 128>>>(A, PK, irnn2_w, irnn2_b);
    // conv3 (128->32) + relu + 1x1 + sigmoid fused
    wprepA_kernel<8><<<144, 256>>>(conv3_w, Af);
    conv_mma_kernel<8><<<mgrid, 256, CM_SMEM>>>(PK, Af, out, conv_out_w, 1);
}